// round 17
// baseline (speedup 1.0000x reference)
#include <cuda_runtime.h>
#include <cuda_fp16.h>
#include <cstdint>

#define N_   8
#define C_   64
#define H_   256
#define W_   256
#define G_   8
#define CPG_ 8               // channels per group
#define ROWS 8               // rows per block strip
#define TR   (ROWS+2)        // tile rows incl. halo
#define CHUNKS (H_/ROWS)     // 32
#define EPS_ 1e-5f
#define NT   128             // pass1: 64 col-groups x 2 row-groups
#define W4_  (W_/4)          // 64
#define TQ   (TR*W4_)        // 640 staging quads (= 5*NT exactly)
#define WP   264             // padded row width: col3 = L-halo, cols4..259 data, col260 = R-halo
#define BUFF (TR*WP)         // floats per tile buffer
#define HW_  (H_*W_)
#define HWQ  (HW_/4)
#define NT2  128             // pass2 threads
#define PXT2 4               // pixels per thread in fused pass2
#define SEG2 (HW_/(NT2*PXT2))// 128 segments per image

typedef unsigned long long u64;

// Static scratch (no runtime allocation)
__device__ float  g_part[N_*G_*CHUNKS*2];
__device__ __half g_conv[(size_t)N_*C_*HW_];        // conv output, fp16 (67 MB)

// ---- f32x2 packed helpers (sm_100+) ----
__device__ __forceinline__ u64 pack2(float lo, float hi) {
    u64 r; asm("mov.b64 %0,{%1,%2};" : "=l"(r) : "f"(lo), "f"(hi)); return r;
}
__device__ __forceinline__ void unpack2(u64 v, float& lo, float& hi) {
    asm("mov.b64 {%0,%1},%2;" : "=f"(lo), "=f"(hi) : "l"(v));
}
__device__ __forceinline__ u64 fma2(u64 a, u64 b, u64 c) {
    u64 d; asm("fma.rn.f32x2 %0,%1,%2,%3;" : "=l"(d) : "l"(a), "l"(b), "l"(c)); return d;
}
__device__ __forceinline__ u64 add2(u64 a, u64 b) {
    u64 d; asm("add.rn.f32x2 %0,%1,%2;" : "=l"(d) : "l"(a), "l"(b)); return d;
}
__device__ __forceinline__ float tanh_fast(float x) {
    float y; asm("tanh.approx.f32 %0,%1;" : "=f"(y) : "f"(x)); return y;
}
__device__ __forceinline__ float ex2_fast(float x) {
    float y; asm("ex2.approx.f32 %0,%1;" : "=f"(y) : "f"(x)); return y;
}

#define CP_COMMIT() asm volatile("cp.async.commit_group;")
#define CP_WAIT1()  asm volatile("cp.async.wait_group 1;")

// Stage one (TR x W_) channel tile gmem -> padded smem rows via cp.async.cg.
__device__ __forceinline__ void cpa_tile(unsigned sbase, const float4* __restrict__ xc4,
                                         int h0, int tid) {
    #pragma unroll
    for (int i = 0; i < 5; ++i) {
        const int idx = tid + i*NT;                 // 5*128 = 640 = TQ exactly
        const int r = idx >> 6, q = idx & (W4_-1);
        const int h = h0 - 1 + r;
        const bool v = (h >= 0) && (h < H_);
        const float4* src = xc4 + (v ? (h*W4_ + q) : q);
        const int sz = v ? 16 : 0;
        const unsigned dst = sbase + (unsigned)(r*WP + 4 + 4*q)*4u;
        asm volatile("cp.async.cg.shared.global [%0], [%1], 16, %2;"
                     :: "r"(dst), "l"(src), "r"(sz));
    }
}

// 5 shifted operand pairs for one tile row, covering 4 pixels (2 f32x2 pairs)
struct RowP { u64 P0, P1, P2, P3, P4; };

__device__ __forceinline__ RowP load_row(const float* rb) {
    RowP p;
    const float  L = rb[-1];
    const float4 M = *(const float4*)rb;            // LDS.128, 16B aligned
    const float  R = rb[4];
    p.P0 = pack2(L,   M.x); p.P1 = pack2(M.x, M.y); p.P2 = pack2(M.y, M.z);
    p.P3 = pack2(M.z, M.w); p.P4 = pack2(M.w, R);
    return p;
}

#define ROW_ACC(r, b, oA, oB)                                             \
    oA = fma2((r).P0, wkp[b],   oA);                                      \
    oA = fma2((r).P1, wkp[b+1], oA);                                      \
    oA = fma2((r).P2, wkp[b+2], oA);                                      \
    oB = fma2((r).P2, wkp[b],   oB);                                      \
    oB = fma2((r).P3, wkp[b+1], oB);                                      \
    oB = fma2((r).P4, wkp[b+2], oB);

// row-sweep 3x3 conv; 1 RowP live at a time. SINK(o, cA, cB) on completion.
#define CONV_SWEEP(tb, wkp, SINK)                                         \
    {                                                                     \
        u64 oA[4] = {0,0,0,0}, oB[4] = {0,0,0,0};                         \
        _Pragma("unroll")                                                 \
        for (int tr = 0; tr < 6; ++tr) {                                  \
            RowP r = load_row((tb) + (4*ty + tr)*WP);                     \
            _Pragma("unroll")                                             \
            for (int o = 0; o < 4; ++o) {                                 \
                if (o >= tr - 2 && o <= tr) {                             \
                    ROW_ACC(r, 3*(tr - o), oA[o], oB[o]);                 \
                }                                                         \
            }                                                             \
            if (tr >= 2) { const int o = tr - 2; SINK(o, oA[o], oB[o]); } \
        }                                                                 \
    }

#define ZERO_HALOS(bufbase)                                               \
    if (tid < 3*TR*2) {                                                   \
        const int b = tid / (TR*2), rest = tid % (TR*2);                  \
        const int row = rest >> 1, col = (rest & 1) ? 260 : 3;            \
        (bufbase)[b*BUFF + row*WP + col] = 0.f;                           \
    }

#define LOAD_WEIGHTS()                                                    \
    if (tid < 9*CPG_) {                                                   \
        const int j = tid / CPG_, cc = tid % CPG_;                        \
        const float w = wgt[j*C_ + g*CPG_ + cc];                          \
        wsm2[j][cc] = make_float2(w, w);                                  \
    }

// ---------------- Pass 1: depthwise conv -> fp16 conv store + per-(n,g,chunk) stats ----------------
__global__ __launch_bounds__(NT, 8) void k_pass1(const float* __restrict__ x,
                                                 const float* __restrict__ wgt) {
    __shared__ __align__(16) float buf[3*BUFF];
    __shared__ float2 wsm2[9][CPG_];
    __shared__ float  red[4], red2[4];

    const int bid   = blockIdx.x;
    const int chunk = bid % CHUNKS;
    const int g     = (bid / CHUNKS) % G_;
    const int n     = bid / (CHUNKS * G_);
    const int h0    = chunk * ROWS;
    const int tid   = threadIdx.x;
    const int tx    = tid & 63;                     // cols 4tx..4tx+3
    const int ty    = tid >> 6;                     // rows 4ty..4ty+3
    const int lane  = tid & 31, wid = tid >> 5;

    ZERO_HALOS(buf);
    LOAD_WEIGHTS();

    const unsigned sb0 = (unsigned)__cvta_generic_to_shared(&buf[0]);
    const float4* x4 = (const float4*)x;
    const size_t plane0 = (size_t)(n*C_ + g*CPG_) * HWQ;

    cpa_tile(sb0,                    x4 + plane0,       h0, tid); CP_COMMIT();
    cpa_tile(sb0 + (unsigned)BUFF*4, x4 + plane0 + HWQ, h0, tid); CP_COMMIT();

    u64 gsP = 0, gs2P = 0;
    int bsel = 0;
    for (int cc = 0; cc < CPG_; ++cc) {
        CP_WAIT1();
        __syncthreads();
        if (cc + 2 < CPG_) {
            const int nb = (bsel + 2 >= 3) ? bsel - 1 : bsel + 2;
            cpa_tile(sb0 + (unsigned)(nb*BUFF)*4, x4 + plane0 + (size_t)(cc+2)*HWQ, h0, tid);
        }
        CP_COMMIT();

        u64 wkp[9];
        #pragma unroll
        for (int j = 0; j < 9; ++j) wkp[j] = *(const u64*)&wsm2[j][cc];

        // conv output pointer for this channel / thread patch (8B aligned)
        __half* cvp = g_conv + ((size_t)(n*C_ + g*CPG_ + cc)*H_ + h0 + 4*ty)*W_ + 4*tx;

        const float* tb = buf + bsel*BUFF + 4 + 4*tx;
        #define SINK1(o, cA, cB)                                          \
            gsP  = add2(gsP, add2(cA, cB));                               \
            gs2P = fma2(cA, cA, gs2P);                                    \
            gs2P = fma2(cB, cB, gs2P);                                    \
            {                                                             \
                float a0, a1, b0, b1;                                     \
                unpack2(cA, a0, a1); unpack2(cB, b0, b1);                 \
                __half2 hA = __floats2half2_rn(a0, a1);                   \
                __half2 hB = __floats2half2_rn(b0, b1);                   \
                uint2 u;                                                  \
                u.x = *(unsigned*)&hA; u.y = *(unsigned*)&hB;             \
                *(uint2*)(cvp + (o)*W_) = u;                              \
            }
        CONV_SWEEP(tb, wkp, SINK1);
        #undef SINK1
        bsel = (bsel + 1 == 3) ? 0 : bsel + 1;
    }

    float a, b, gs, gs2;
    unpack2(gsP,  a, b); gs  = a + b;
    unpack2(gs2P, a, b); gs2 = a + b;
    #pragma unroll
    for (int off = 16; off; off >>= 1) {
        gs  += __shfl_down_sync(0xffffffffu, gs,  off);
        gs2 += __shfl_down_sync(0xffffffffu, gs2, off);
    }
    if (lane == 0) { red[wid] = gs; red2[wid] = gs2; }
    __syncthreads();
    if (tid == 0) {
        float s  = red[0] + red[1] + red[2] + red[3];
        float s2 = red2[0] + red2[1] + red2[2] + red2[3];
        const int idx = ((n*G_ + g)*CHUNKS + chunk)*2;
        g_part[idx]   = s;
        g_part[idx+1] = s2;
    }
}

// ---------------- Pass 2 (fused, 4 px/thread): stream fp16 conv across ALL channels,
// norm/act/residual/exp-sum -> log -> broadcast 64-channel write.
__global__ __launch_bounds__(NT2) void k_pass2(float* __restrict__ out) {
    __shared__ float s_rstd[G_], s_nmr[G_];

    const int bid = blockIdx.x;
    const int seg = bid % SEG2;
    const int n   = bid / SEG2;
    const int tid = threadIdx.x;

    // stats: 8 groups x 16-lane segments; lane l sums chunks l and l+16
    {
        const int g = tid >> 4, l = tid & 15;
        const int sg = (n*G_ + g)*CHUNKS;
        float s  = g_part[(sg + l)*2]     + g_part[(sg + l + 16)*2];
        float s2 = g_part[(sg + l)*2 + 1] + g_part[(sg + l + 16)*2 + 1];
        #pragma unroll
        for (int off = 8; off; off >>= 1) {
            s  += __shfl_down_sync(0xffffffffu, s,  off, 16);
            s2 += __shfl_down_sync(0xffffffffu, s2, off, 16);
        }
        if (l == 0) {
            const float inv = 1.0f / (float)(CPG_*H_*W_);
            const float m = s * inv;
            const float v = s2 * inv - m*m;
            const float r = rsqrtf(v + EPS_);
            s_rstd[g] = m; // placeholder, fixed below
            s_rstd[g] = r;
            s_nmr[g]  = -m * r;
        }
    }
    __syncthreads();

    const int px = seg*(NT2*PXT2) + tid*PXT2;       // 4 consecutive pixels (16B aligned)
    const float L2E = 1.4426950408889634f;

    const __half* cvb = g_conv + (size_t)n*C_*HW_ + px;

    float es[PXT2];
    #pragma unroll
    for (int i = 0; i < PXT2; ++i) es[i] = 0.f;

    #pragma unroll 8
    for (int c = 0; c < C_; ++c) {
        const uint2 u = *(const uint2*)(cvb + (size_t)c*HW_);     // 4 halves
        const float2 fa = __half22float2(*(const __half2*)&u.x);
        const float2 fb = __half22float2(*(const __half2*)&u.y);
        const float f[4] = { fa.x, fa.y, fb.x, fb.y };
        const int g = c >> 3;
        const float rstd = s_rstd[g], nmr = s_nmr[g];
        #pragma unroll
        for (int k = 0; k < 4; ++k) {
            const float cv = f[k];
            const float v  = fmaf(cv, rstd, nmr);
            const float t  = tanh_fast(v);
            // t in (-1,1) => clip(t+3,0,6) == t+3: xr = cv + t*(t+3)/6
            const float xr = fmaf(t * (1.0f/6.0f), t + 3.0f, cv);
            es[k] += ex2_fast(xr * L2E);
        }
    }

    float4 L;
    L.x = __logf(es[0]); L.y = __logf(es[1]);
    L.z = __logf(es[2]); L.w = __logf(es[3]);

    float* ob = out + (size_t)n*C_*HW_ + px;
    #pragma unroll
    for (int c = 0; c < C_; ++c)
        __stcs((float4*)(ob + (size_t)c*HW_), L);
}

extern "C" void kernel_launch(void* const* d_in, const int* in_sizes, int n_in,
                              void* d_out, int out_size) {
    const float* x   = (const float*)d_in[0];       // [8,64,256,256]
    const float* wgt = (const float*)d_in[1];       // [3,3,64]
    float* out = (float*)d_out;

    k_pass1<<<N_*G_*CHUNKS, NT>>>(x, wgt);
    k_pass2<<<N_*SEG2, NT2>>>(out);
}